// round 4
// baseline (speedup 1.0000x reference)
#include <cuda_runtime.h>
#include <cstdint>

#define NROWS 16384
#define DDIM  17          // DATA_DIM + 1
#define DH    64
#define LENM  1088
#define MPRI  65
#define NM0   100
#define NM1   100
#define TILE_N 128
#define NTH    320

// Scratch for sampled weights (device globals — no allocation allowed)
__device__ float g_W0t[NM0 * LENM];   // [m][d*64+h]
__device__ float g_W1[MPRI * NM1];    // [d][c]

// ---------------------------------------------------------------------------
// Threefry-2x32 (exact JAX algorithm)
// ---------------------------------------------------------------------------
__device__ __forceinline__ uint32_t rotl32(uint32_t v, int r) {
    return (v << r) | (v >> (32 - r));
}

__device__ __forceinline__ void threefry2x32(uint32_t k0, uint32_t k1,
                                             uint32_t x0, uint32_t x1,
                                             uint32_t& o0, uint32_t& o1) {
    uint32_t k2 = k0 ^ k1 ^ 0x1BD11BDAu;
    x0 += k0; x1 += k1;
#define TF_R(r) { x0 += x1; x1 = rotl32(x1, (r)); x1 ^= x0; }
    TF_R(13) TF_R(15) TF_R(26) TF_R(6)
    x0 += k1; x1 += k2 + 1u;
    TF_R(17) TF_R(29) TF_R(16) TF_R(24)
    x0 += k2; x1 += k0 + 2u;
    TF_R(13) TF_R(15) TF_R(26) TF_R(6)
    x0 += k0; x1 += k1 + 3u;
    TF_R(17) TF_R(29) TF_R(16) TF_R(24)
    x0 += k1; x1 += k2 + 4u;
    TF_R(13) TF_R(15) TF_R(26) TF_R(6)
    x0 += k2; x1 += k0 + 5u;
#undef TF_R
    o0 = x0; o1 = x1;
}

// Partitionable-mode 32-bit random bits for linear index i (< 2^32):
// bits = out0 ^ out1 of threefry(key, hi=0, lo=i)
__device__ __forceinline__ uint32_t random_bits_part(uint32_t k0, uint32_t k1, uint32_t i) {
    uint32_t o0, o1;
    threefry2x32(k0, k1, 0u, i, o0, o1);
    return o0 ^ o1;
}

// XLA's f32 ErfInv polynomial (Giles), matches jax.lax.erf_inv lowering
__device__ __forceinline__ float erfinv_xla(float x) {
    float w = -log1pf(-x * x);
    float p;
    if (w < 5.0f) {
        w -= 2.5f;
        p = 2.81022636e-08f;
        p = fmaf(p, w, 3.43273939e-07f);
        p = fmaf(p, w, -3.5233877e-06f);
        p = fmaf(p, w, -4.39150654e-06f);
        p = fmaf(p, w, 0.00021858087f);
        p = fmaf(p, w, -0.00125372503f);
        p = fmaf(p, w, -0.00417768164f);
        p = fmaf(p, w, 0.246640727f);
        p = fmaf(p, w, 1.50140941f);
    } else {
        w = sqrtf(w) - 3.0f;
        p = -0.000200214257f;
        p = fmaf(p, w, 0.000100950558f);
        p = fmaf(p, w, 0.00134934322f);
        p = fmaf(p, w, -0.00367342844f);
        p = fmaf(p, w, 0.00573950773f);
        p = fmaf(p, w, -0.0076224613f);
        p = fmaf(p, w, 0.00943887047f);
        p = fmaf(p, w, 1.00167406f);
        p = fmaf(p, w, 2.83297682f);
    }
    return p * x;
}

// bits -> jax.random.normal sample: uniform in (nextafter(-1,0), 1), sqrt(2)*erfinv
__device__ __forceinline__ float bits_to_normal(uint32_t b) {
    float f = __uint_as_float((b >> 9) | 0x3f800000u) - 1.0f;   // [0,1)
    const float lo = -0.99999994f;          // nextafter(-1, 0) in f32
    const float diff = 2.0f;                // (1 - lo) rounded in f32
    float u = fmaf(f, diff, lo);
    u = fmaxf(u, lo);
    return 1.41421356f * erfinv_xla(u);
}

// ---------------------------------------------------------------------------
// Prep kernel: sample W0, W1 via partitionable threefry; write output tail
// ---------------------------------------------------------------------------
#define EPS0_TOT (LENM * NM0)     // 108800
#define EPS1_TOT (MPRI * NM1)     // 6500

__global__ void prep_kernel(const float* __restrict__ ms_vs, float* __restrict__ out) {
    int tid = blockIdx.x * blockDim.x + threadIdx.x;

    // split(key42): subkey i = BOTH output words of threefry(key, hi=0, lo=i)
    uint32_t k0a, k0b, k1a, k1b;
    threefry2x32(0u, 42u, 0u, 0u, k0a, k0b);   // subkey 0
    threefry2x32(0u, 42u, 0u, 1u, k1a, k1b);   // subkey 1

    if (tid < EPS0_TOT) {
        // eps0 shape (1088, 100), linear index tid = r*100 + m
        int r = tid / NM0, m = tid % NM0;
        uint32_t b = random_bits_part(k0a, k0b, (uint32_t)tid);
        float v = fabsf(ms_vs[LENM + MPRI + r]) + 1e-6f;
        g_W0t[m * LENM + r] = fmaf(bits_to_normal(b), sqrtf(v), ms_vs[r]);
    } else if (tid < EPS0_TOT + EPS1_TOT) {
        // eps1 shape (65, 100), linear index i = r*100 + c
        int i = tid - EPS0_TOT;
        int r = i / NM1, c = i % NM1;
        uint32_t b = random_bits_part(k1a, k1b, (uint32_t)i);
        float v = fabsf(ms_vs[2 * LENM + MPRI + r]) + 1e-6f;
        g_W1[r * NM1 + c] = fmaf(bits_to_normal(b), sqrtf(v), ms_vs[LENM + r]);
    }

    // Output tail: m_w0 (1088), v_w0 (1088), m_pri (65), v_pri (65)
    long long base = (long long)NROWS * NM0 * NM1;
    if (tid < LENM) {
        out[base + tid]        = ms_vs[tid];
        out[base + LENM + tid] = fabsf(ms_vs[LENM + MPRI + tid]) + 1e-6f;
    }
    if (tid < MPRI) {
        out[base + 2 * LENM + tid]        = ms_vs[LENM + tid];
        out[base + 2 * LENM + MPRI + tid] = fabsf(ms_vs[2 * LENM + MPRI + tid]) + 1e-6f;
    }
}

// ---------------------------------------------------------------------------
// Main kernel: one block per (n-tile of 128, m). Phase A: Z = relu(x @ W0_m)
// in shared; Phase B: 128x100 register-blocked GEMM [1,Z] @ W1.
// ---------------------------------------------------------------------------
#define SMEM_FLOATS (TILE_N * DDIM + DDIM * DH + MPRI * NM1 + MPRI * TILE_N)
#define SMEM_BYTES  (SMEM_FLOATS * 4)

extern __shared__ float sm_buf[];

__global__ __launch_bounds__(NTH) void main_kernel(const float* __restrict__ x,
                                                   float* __restrict__ out) {
    float* xs  = sm_buf;                      // [128][17]
    float* W0s = xs + TILE_N * DDIM;          // [17][64]
    float* W1s = W0s + DDIM * DH;             // [65][100]
    float* Zs  = W1s + MPRI * NM1;            // [65][128], row 0 = ones

    const int m   = blockIdx.y;
    const int n0  = blockIdx.x * TILE_N;
    const int tid = threadIdx.x;

    // Stage inputs (all coalesced)
    for (int i = tid; i < TILE_N * DDIM; i += NTH)
        xs[i] = x[n0 * DDIM + i];
    for (int i = tid; i < LENM; i += NTH)
        W0s[i] = g_W0t[m * LENM + i];         // [d*64+h] layout == [d][h]
    for (int i = tid; i < MPRI * NM1; i += NTH)
        W1s[i] = g_W1[i];
    for (int i = tid; i < TILE_N; i += NTH)
        Zs[i] = 1.0f;                          // bias row
    __syncthreads();

    // Phase A: Z[1+h][n] = relu(x[n] . W0[:, h])
    for (int idx = tid; idx < DH * TILE_N; idx += NTH) {
        int h = idx >> 7;          // / 128
        int n = idx & (TILE_N - 1);
        float acc = 0.0f;
        const float* xr = &xs[n * DDIM];
#pragma unroll
        for (int d = 0; d < DDIM; d++)
            acc = fmaf(xr[d], W0s[d * DH + h], acc);
        Zs[(1 + h) * TILE_N + n] = fmaxf(acc, 0.0f);
    }
    __syncthreads();

    // Phase B: per thread 8 rows x 5 cols; cols at tx + 20*c (coalesced stores)
    const int tx = tid % 20;
    const int ty = tid / 20;       // 0..15 -> rows ty*8..ty*8+7

    float acc[8][5];
#pragma unroll
    for (int c = 0; c < 5; c++) {
        float w0 = W1s[tx + 20 * c];           // d=0 row (ones) contribution
#pragma unroll
        for (int r = 0; r < 8; r++) acc[r][c] = w0;
    }

#pragma unroll 4
    for (int dd = 1; dd < MPRI; dd++) {
        const float4 za = *(const float4*)&Zs[dd * TILE_N + ty * 8];
        const float4 zb = *(const float4*)&Zs[dd * TILE_N + ty * 8 + 4];
        float z[8] = {za.x, za.y, za.z, za.w, zb.x, zb.y, zb.z, zb.w};
#pragma unroll
        for (int c = 0; c < 5; c++) {
            float w = W1s[dd * NM1 + tx + 20 * c];
#pragma unroll
            for (int r = 0; r < 8; r++)
                acc[r][c] = fmaf(z[r], w, acc[r][c]);
        }
    }

    // Store: out[n*10000 + m*100 + col]
#pragma unroll
    for (int r = 0; r < 8; r++) {
        long long row = (long long)(n0 + ty * 8 + r) * (NM0 * NM1) + (long long)m * NM1;
#pragma unroll
        for (int c = 0; c < 5; c++)
            out[row + tx + 20 * c] = acc[r][c];
    }
}

// ---------------------------------------------------------------------------
extern "C" void kernel_launch(void* const* d_in, const int* in_sizes, int n_in,
                              void* d_out, int out_size) {
    const float* x     = (const float*)d_in[0];   // (16384, 17) f32
    const float* ms_vs = (const float*)d_in[1];   // (2306,) f32
    float* out = (float*)d_out;

    cudaFuncSetAttribute(main_kernel,
                         cudaFuncAttributeMaxDynamicSharedMemorySize, SMEM_BYTES);

    // 1) sample weights + write tail outputs
    int prep_threads = EPS0_TOT + EPS1_TOT;       // 115300
    prep_kernel<<<(prep_threads + 255) / 256, 256>>>(ms_vs, out);

    // 2) main compute
    dim3 grid(NROWS / TILE_N, NM0);
    main_kernel<<<grid, NTH, SMEM_BYTES>>>(x, out);
}

// round 5
// speedup vs baseline: 1.3346x; 1.3346x over previous
#include <cuda_runtime.h>
#include <cstdint>

#define NROWS 16384
#define DDIM  17          // DATA_DIM + 1
#define DH    64
#define LENM  1088
#define MPRI  65
#define NM0   100
#define NM1   100
#define TILE_N 128
#define NTH    160

typedef unsigned long long ull;

// Scratch for sampled weights (device globals — no allocation allowed)
__device__ float g_W0t[NM0 * LENM];   // [m][d*64+h]
__device__ float g_W1[MPRI * NM1];    // [d][c]

// ---------------------------------------------------------------------------
// Packed fp32x2 helpers (Blackwell FFMA2 — only reachable via PTX)
// ---------------------------------------------------------------------------
__device__ __forceinline__ ull fma2(ull a, ull b, ull c) {
    ull d;
    asm("fma.rn.f32x2 %0, %1, %2, %3;" : "=l"(d) : "l"(a), "l"(b), "l"(c));
    return d;
}
__device__ __forceinline__ ull pack2(float lo, float hi) {
    ull d;
    asm("mov.b64 %0, {%1, %2};" : "=l"(d) : "f"(lo), "f"(hi));
    return d;
}
__device__ __forceinline__ float2 unpack2(ull v) {
    float2 r;
    asm("mov.b64 {%0, %1}, %2;" : "=f"(r.x), "=f"(r.y) : "l"(v));
    return r;
}

// ---------------------------------------------------------------------------
// Threefry-2x32 (exact JAX algorithm, partitionable mode)
// ---------------------------------------------------------------------------
__device__ __forceinline__ uint32_t rotl32(uint32_t v, int r) {
    return (v << r) | (v >> (32 - r));
}

__device__ __forceinline__ void threefry2x32(uint32_t k0, uint32_t k1,
                                             uint32_t x0, uint32_t x1,
                                             uint32_t& o0, uint32_t& o1) {
    uint32_t k2 = k0 ^ k1 ^ 0x1BD11BDAu;
    x0 += k0; x1 += k1;
#define TF_R(r) { x0 += x1; x1 = rotl32(x1, (r)); x1 ^= x0; }
    TF_R(13) TF_R(15) TF_R(26) TF_R(6)
    x0 += k1; x1 += k2 + 1u;
    TF_R(17) TF_R(29) TF_R(16) TF_R(24)
    x0 += k2; x1 += k0 + 2u;
    TF_R(13) TF_R(15) TF_R(26) TF_R(6)
    x0 += k0; x1 += k1 + 3u;
    TF_R(17) TF_R(29) TF_R(16) TF_R(24)
    x0 += k1; x1 += k2 + 4u;
    TF_R(13) TF_R(15) TF_R(26) TF_R(6)
    x0 += k2; x1 += k0 + 5u;
#undef TF_R
    o0 = x0; o1 = x1;
}

__device__ __forceinline__ uint32_t random_bits_part(uint32_t k0, uint32_t k1, uint32_t i) {
    uint32_t o0, o1;
    threefry2x32(k0, k1, 0u, i, o0, o1);
    return o0 ^ o1;
}

// XLA's f32 ErfInv polynomial (Giles)
__device__ __forceinline__ float erfinv_xla(float x) {
    float w = -log1pf(-x * x);
    float p;
    if (w < 5.0f) {
        w -= 2.5f;
        p = 2.81022636e-08f;
        p = fmaf(p, w, 3.43273939e-07f);
        p = fmaf(p, w, -3.5233877e-06f);
        p = fmaf(p, w, -4.39150654e-06f);
        p = fmaf(p, w, 0.00021858087f);
        p = fmaf(p, w, -0.00125372503f);
        p = fmaf(p, w, -0.00417768164f);
        p = fmaf(p, w, 0.246640727f);
        p = fmaf(p, w, 1.50140941f);
    } else {
        w = sqrtf(w) - 3.0f;
        p = -0.000200214257f;
        p = fmaf(p, w, 0.000100950558f);
        p = fmaf(p, w, 0.00134934322f);
        p = fmaf(p, w, -0.00367342844f);
        p = fmaf(p, w, 0.00573950773f);
        p = fmaf(p, w, -0.0076224613f);
        p = fmaf(p, w, 0.00943887047f);
        p = fmaf(p, w, 1.00167406f);
        p = fmaf(p, w, 2.83297682f);
    }
    return p * x;
}

__device__ __forceinline__ float bits_to_normal(uint32_t b) {
    float f = __uint_as_float((b >> 9) | 0x3f800000u) - 1.0f;
    const float lo = -0.99999994f;
    const float diff = 2.0f;
    float u = fmaf(f, diff, lo);
    u = fmaxf(u, lo);
    return 1.41421356f * erfinv_xla(u);
}

// ---------------------------------------------------------------------------
// Prep kernel: sample W0, W1 via partitionable threefry; write output tail
// ---------------------------------------------------------------------------
#define EPS0_TOT (LENM * NM0)     // 108800
#define EPS1_TOT (MPRI * NM1)     // 6500

__global__ void prep_kernel(const float* __restrict__ ms_vs, float* __restrict__ out) {
    int tid = blockIdx.x * blockDim.x + threadIdx.x;

    uint32_t k0a, k0b, k1a, k1b;
    threefry2x32(0u, 42u, 0u, 0u, k0a, k0b);   // subkey 0
    threefry2x32(0u, 42u, 0u, 1u, k1a, k1b);   // subkey 1

    if (tid < EPS0_TOT) {
        int r = tid / NM0, m = tid % NM0;
        uint32_t b = random_bits_part(k0a, k0b, (uint32_t)tid);
        float v = fabsf(ms_vs[LENM + MPRI + r]) + 1e-6f;
        g_W0t[m * LENM + r] = fmaf(bits_to_normal(b), sqrtf(v), ms_vs[r]);
    } else if (tid < EPS0_TOT + EPS1_TOT) {
        int i = tid - EPS0_TOT;
        int r = i / NM1, c = i % NM1;
        uint32_t b = random_bits_part(k1a, k1b, (uint32_t)i);
        float v = fabsf(ms_vs[2 * LENM + MPRI + r]) + 1e-6f;
        g_W1[r * NM1 + c] = fmaf(bits_to_normal(b), sqrtf(v), ms_vs[LENM + r]);
    }

    long long base = (long long)NROWS * NM0 * NM1;
    if (tid < LENM) {
        out[base + tid]        = ms_vs[tid];
        out[base + LENM + tid] = fabsf(ms_vs[LENM + MPRI + tid]) + 1e-6f;
    }
    if (tid < MPRI) {
        out[base + 2 * LENM + tid]        = ms_vs[LENM + tid];
        out[base + 2 * LENM + MPRI + tid] = fabsf(ms_vs[2 * LENM + MPRI + tid]) + 1e-6f;
    }
}

// ---------------------------------------------------------------------------
// Main kernel: one block per (n-tile of 128, m).
// Phase A: Z = relu(x @ W0_m), per-thread-per-row, packed h-pairs (FFMA2).
// Phase B: 128x100 register-blocked GEMM [1,Z] @ W1 with FFMA2:
//   160 threads, per-thread 8 rows x 5 col-pairs (10 cols).
// ---------------------------------------------------------------------------
#define SMEM_FLOATS (TILE_N * DDIM + DDIM * DH + MPRI * NM1 + MPRI * TILE_N)
#define SMEM_BYTES  (SMEM_FLOATS * 4)

extern __shared__ float sm_buf[];

__global__ __launch_bounds__(NTH, 3) void main_kernel(const float* __restrict__ x,
                                                      float* __restrict__ out) {
    float* xs  = sm_buf;                      // [128][17]
    float* W0s = xs + TILE_N * DDIM;          // [17][64]
    float* W1s = W0s + DDIM * DH;             // [65][100]
    float* Zs  = W1s + MPRI * NM1;            // [65][128], row 0 = ones

    const int m   = blockIdx.y;
    const int n0  = blockIdx.x * TILE_N;
    const int tid = threadIdx.x;

    // Stage inputs (coalesced)
    for (int i = tid; i < TILE_N * DDIM; i += NTH)
        xs[i] = x[n0 * DDIM + i];
    for (int i = tid; i < LENM; i += NTH)
        W0s[i] = g_W0t[m * LENM + i];         // [d][h], h contiguous
    for (int i = tid; i < MPRI * NM1; i += NTH)
        W1s[i] = g_W1[i];
    for (int i = tid; i < TILE_N; i += NTH)
        Zs[i] = 1.0f;                          // bias row
    __syncthreads();

    // Phase A: thread tid (<128) owns row n=tid. Packed over h-pairs.
    if (tid < TILE_N) {
        ull xr2[DDIM];
#pragma unroll
        for (int d = 0; d < DDIM; d++) {
            float v = xs[tid * DDIM + d];
            xr2[d] = pack2(v, v);
        }
        for (int h4 = 0; h4 < DH / 4; h4++) {
            ull a0 = 0ULL, a1 = 0ULL;   // (h,h+1), (h+2,h+3)
#pragma unroll
            for (int d = 0; d < DDIM; d++) {
                // LDS.128 broadcast: two packed fp32 pairs
                const ulonglong2 w2 = *(const ulonglong2*)&W0s[d * DH + h4 * 4];
                a0 = fma2(xr2[d], w2.x, a0);
                a1 = fma2(xr2[d], w2.y, a1);
            }
            float2 r0 = unpack2(a0), r1 = unpack2(a1);
            int h = h4 * 4;
            Zs[(1 + h) * TILE_N + tid] = fmaxf(r0.x, 0.0f);
            Zs[(2 + h) * TILE_N + tid] = fmaxf(r0.y, 0.0f);
            Zs[(3 + h) * TILE_N + tid] = fmaxf(r1.x, 0.0f);
            Zs[(4 + h) * TILE_N + tid] = fmaxf(r1.y, 0.0f);
        }
    }
    __syncthreads();

    // Phase B: 8 rows x 5 col-pairs per thread, all FMAs packed.
    const int tx = tid % 10;        // col-pair group: cols 2*tx + 20*c
    const int ty = tid / 10;        // 0..15 -> rows ty*8 .. ty*8+7

    ull acc[8][5];
#pragma unroll
    for (int c = 0; c < 5; c++) {
        ull w0 = *(const ull*)&W1s[2 * tx + 20 * c];   // ones-row contribution
#pragma unroll
        for (int r = 0; r < 8; r++) acc[r][c] = w0;
    }

#pragma unroll 2
    for (int dd = 1; dd < MPRI; dd++) {
        const float4 za = *(const float4*)&Zs[dd * TILE_N + ty * 8];
        const float4 zb = *(const float4*)&Zs[dd * TILE_N + ty * 8 + 4];
        ull z2[8];
        z2[0] = pack2(za.x, za.x); z2[1] = pack2(za.y, za.y);
        z2[2] = pack2(za.z, za.z); z2[3] = pack2(za.w, za.w);
        z2[4] = pack2(zb.x, zb.x); z2[5] = pack2(zb.y, zb.y);
        z2[6] = pack2(zb.z, zb.z); z2[7] = pack2(zb.w, zb.w);
        const float* wrow = &W1s[dd * NM1 + 2 * tx];
#pragma unroll
        for (int c = 0; c < 5; c++) {
            ull w = *(const ull*)&wrow[20 * c];        // LDS.64, no repack
#pragma unroll
            for (int r = 0; r < 8; r++)
                acc[r][c] = fma2(z2[r], w, acc[r][c]);
        }
    }

    // Store: out[n*10000 + m*100 + 2*tx + 20*c], 8-byte vector stores
#pragma unroll
    for (int r = 0; r < 8; r++) {
        long long row = (long long)(n0 + ty * 8 + r) * (NM0 * NM1)
                      + (long long)m * NM1 + 2 * tx;
#pragma unroll
        for (int c = 0; c < 5; c++)
            *(ull*)&out[row + 20 * c] = acc[r][c];
    }
}

// ---------------------------------------------------------------------------
extern "C" void kernel_launch(void* const* d_in, const int* in_sizes, int n_in,
                              void* d_out, int out_size) {
    const float* x     = (const float*)d_in[0];   // (16384, 17) f32
    const float* ms_vs = (const float*)d_in[1];   // (2306,) f32
    float* out = (float*)d_out;

    cudaFuncSetAttribute(main_kernel,
                         cudaFuncAttributeMaxDynamicSharedMemorySize, SMEM_BYTES);

    int prep_threads = EPS0_TOT + EPS1_TOT;       // 115300
    prep_kernel<<<(prep_threads + 255) / 256, 256>>>(ms_vs, out);

    dim3 grid(NROWS / TILE_N, NM0);
    main_kernel<<<grid, NTH, SMEM_BYTES>>>(x, out);
}

// round 6
// speedup vs baseline: 1.4426x; 1.0809x over previous
#include <cuda_runtime.h>
#include <cstdint>

#define NROWS 16384
#define DDIM  17          // DATA_DIM + 1
#define DH    64
#define LENM  1088
#define MPRI  65
#define NM0   100
#define NM1   100
#define TILE_N 128
#define NTH    160

typedef unsigned long long ull;

// Scratch for sampled weights (device globals — no allocation allowed)
__device__ float g_W0t[NM0 * LENM];   // [m][d*64+h]
__device__ float g_W1[MPRI * NM1];    // [d][c]

// ---------------------------------------------------------------------------
// Packed fp32x2 helpers (Blackwell FFMA2 — only reachable via PTX)
// ---------------------------------------------------------------------------
__device__ __forceinline__ ull fma2(ull a, ull b, ull c) {
    ull d;
    asm("fma.rn.f32x2 %0, %1, %2, %3;" : "=l"(d) : "l"(a), "l"(b), "l"(c));
    return d;
}
__device__ __forceinline__ ull pack2(float lo, float hi) {
    ull d;
    asm("mov.b64 %0, {%1, %2};" : "=l"(d) : "f"(lo), "f"(hi));
    return d;
}
__device__ __forceinline__ float2 unpack2(ull v) {
    float2 r;
    asm("mov.b64 {%0, %1}, %2;" : "=f"(r.x), "=f"(r.y) : "l"(v));
    return r;
}

// ---------------------------------------------------------------------------
// Threefry-2x32 (exact JAX algorithm, partitionable mode)
// ---------------------------------------------------------------------------
__device__ __forceinline__ uint32_t rotl32(uint32_t v, int r) {
    return (v << r) | (v >> (32 - r));
}

__device__ __forceinline__ void threefry2x32(uint32_t k0, uint32_t k1,
                                             uint32_t x0, uint32_t x1,
                                             uint32_t& o0, uint32_t& o1) {
    uint32_t k2 = k0 ^ k1 ^ 0x1BD11BDAu;
    x0 += k0; x1 += k1;
#define TF_R(r) { x0 += x1; x1 = rotl32(x1, (r)); x1 ^= x0; }
    TF_R(13) TF_R(15) TF_R(26) TF_R(6)
    x0 += k1; x1 += k2 + 1u;
    TF_R(17) TF_R(29) TF_R(16) TF_R(24)
    x0 += k2; x1 += k0 + 2u;
    TF_R(13) TF_R(15) TF_R(26) TF_R(6)
    x0 += k0; x1 += k1 + 3u;
    TF_R(17) TF_R(29) TF_R(16) TF_R(24)
    x0 += k1; x1 += k2 + 4u;
    TF_R(13) TF_R(15) TF_R(26) TF_R(6)
    x0 += k2; x1 += k0 + 5u;
#undef TF_R
    o0 = x0; o1 = x1;
}

__device__ __forceinline__ uint32_t random_bits_part(uint32_t k0, uint32_t k1, uint32_t i) {
    uint32_t o0, o1;
    threefry2x32(k0, k1, 0u, i, o0, o1);
    return o0 ^ o1;
}

// XLA's f32 ErfInv polynomial (Giles)
__device__ __forceinline__ float erfinv_xla(float x) {
    float w = -log1pf(-x * x);
    float p;
    if (w < 5.0f) {
        w -= 2.5f;
        p = 2.81022636e-08f;
        p = fmaf(p, w, 3.43273939e-07f);
        p = fmaf(p, w, -3.5233877e-06f);
        p = fmaf(p, w, -4.39150654e-06f);
        p = fmaf(p, w, 0.00021858087f);
        p = fmaf(p, w, -0.00125372503f);
        p = fmaf(p, w, -0.00417768164f);
        p = fmaf(p, w, 0.246640727f);
        p = fmaf(p, w, 1.50140941f);
    } else {
        w = sqrtf(w) - 3.0f;
        p = -0.000200214257f;
        p = fmaf(p, w, 0.000100950558f);
        p = fmaf(p, w, 0.00134934322f);
        p = fmaf(p, w, -0.00367342844f);
        p = fmaf(p, w, 0.00573950773f);
        p = fmaf(p, w, -0.0076224613f);
        p = fmaf(p, w, 0.00943887047f);
        p = fmaf(p, w, 1.00167406f);
        p = fmaf(p, w, 2.83297682f);
    }
    return p * x;
}

__device__ __forceinline__ float bits_to_normal(uint32_t b) {
    float f = __uint_as_float((b >> 9) | 0x3f800000u) - 1.0f;
    const float lo = -0.99999994f;
    const float diff = 2.0f;
    float u = fmaf(f, diff, lo);
    u = fmaxf(u, lo);
    return 1.41421356f * erfinv_xla(u);
}

// ---------------------------------------------------------------------------
// Prep kernel: sample W0, W1 via partitionable threefry; write output tail
// ---------------------------------------------------------------------------
#define EPS0_TOT (LENM * NM0)     // 108800
#define EPS1_TOT (MPRI * NM1)     // 6500

__global__ void prep_kernel(const float* __restrict__ ms_vs, float* __restrict__ out) {
    int tid = blockIdx.x * blockDim.x + threadIdx.x;

    uint32_t k0a, k0b, k1a, k1b;
    threefry2x32(0u, 42u, 0u, 0u, k0a, k0b);   // subkey 0
    threefry2x32(0u, 42u, 0u, 1u, k1a, k1b);   // subkey 1

    if (tid < EPS0_TOT) {
        int r = tid / NM0, m = tid % NM0;
        uint32_t b = random_bits_part(k0a, k0b, (uint32_t)tid);
        float v = fabsf(ms_vs[LENM + MPRI + r]) + 1e-6f;
        g_W0t[m * LENM + r] = fmaf(bits_to_normal(b), sqrtf(v), ms_vs[r]);
    } else if (tid < EPS0_TOT + EPS1_TOT) {
        int i = tid - EPS0_TOT;
        int r = i / NM1, c = i % NM1;
        uint32_t b = random_bits_part(k1a, k1b, (uint32_t)i);
        float v = fabsf(ms_vs[2 * LENM + MPRI + r]) + 1e-6f;
        g_W1[r * NM1 + c] = fmaf(bits_to_normal(b), sqrtf(v), ms_vs[LENM + r]);
    }

    long long base = (long long)NROWS * NM0 * NM1;
    if (tid < LENM) {
        out[base + tid]        = ms_vs[tid];
        out[base + LENM + tid] = fabsf(ms_vs[LENM + MPRI + tid]) + 1e-6f;
    }
    if (tid < MPRI) {
        out[base + 2 * LENM + tid]        = ms_vs[LENM + tid];
        out[base + 2 * LENM + MPRI + tid] = fabsf(ms_vs[2 * LENM + MPRI + tid]) + 1e-6f;
    }
}

// ---------------------------------------------------------------------------
// Main kernel: one block per (n-tile of 128, m).
// Phase A: Z = relu(x @ W0_m); x read directly from global (L2-resident).
// Phase B: 128x100 FFMA2 GEMM, software-pipelined LDS double buffering.
// ---------------------------------------------------------------------------
#define SMEM_FLOATS (DDIM * DH + MPRI * NM1 + MPRI * TILE_N)
#define SMEM_BYTES  (SMEM_FLOATS * 4)

extern __shared__ float sm_buf[];

__global__ __launch_bounds__(NTH, 3) void main_kernel(const float* __restrict__ x,
                                                      float* __restrict__ out) {
    float* W0s = sm_buf;                      // [17][64]
    float* W1s = W0s + DDIM * DH;             // [65][100]
    float* Zs  = W1s + MPRI * NM1;            // [65][128], row 0 = ones

    const int m   = blockIdx.y;
    const int n0  = blockIdx.x * TILE_N;
    const int tid = threadIdx.x;

    // Stage weights (coalesced)
    for (int i = tid; i < LENM; i += NTH)
        W0s[i] = g_W0t[m * LENM + i];         // [d][h], h contiguous
    for (int i = tid; i < MPRI * NM1; i += NTH)
        W1s[i] = g_W1[i];
    for (int i = tid; i < TILE_N; i += NTH)
        Zs[i] = 1.0f;                          // bias row
    __syncthreads();

    // Phase A: thread tid (<128) owns row n=tid; x straight from global/L2.
    if (tid < TILE_N) {
        const float* xr = x + (long long)(n0 + tid) * DDIM;
        ull xr2[DDIM];
#pragma unroll
        for (int d = 0; d < DDIM; d++) {
            float v = __ldg(&xr[d]);
            xr2[d] = pack2(v, v);
        }
#pragma unroll
        for (int h4 = 0; h4 < DH / 4; h4++) {
            ull a0 = 0ULL, a1 = 0ULL;
#pragma unroll
            for (int d = 0; d < DDIM; d++) {
                const ulonglong2 w2 = *(const ulonglong2*)&W0s[d * DH + h4 * 4];
                a0 = fma2(xr2[d], w2.x, a0);
                a1 = fma2(xr2[d], w2.y, a1);
            }
            float2 r0 = unpack2(a0), r1 = unpack2(a1);
            int h = h4 * 4;
            Zs[(1 + h) * TILE_N + tid] = fmaxf(r0.x, 0.0f);
            Zs[(2 + h) * TILE_N + tid] = fmaxf(r0.y, 0.0f);
            Zs[(3 + h) * TILE_N + tid] = fmaxf(r1.x, 0.0f);
            Zs[(4 + h) * TILE_N + tid] = fmaxf(r1.y, 0.0f);
        }
    }
    __syncthreads();

    // Phase B: 8 rows x 5 col-pairs per thread, double-buffered LDS pipeline.
    const int tx = tid % 10;        // col-pair group: cols 2*tx + 20*c
    const int ty = tid / 10;        // 0..15 -> rows ty*8 .. ty*8+7
    const float* Zrow = &Zs[ty * 8];
    const float* Wcol = &W1s[2 * tx];

    ull acc[8][5];
#pragma unroll
    for (int c = 0; c < 5; c++) {
        ull w0 = *(const ull*)&Wcol[20 * c];   // ones-row contribution
#pragma unroll
        for (int r = 0; r < 8; r++) acc[r][c] = w0;
    }

    // prefetch dd = 1
    float4 zaB[2], zbB[2];
    ull wB[2][5];
    zaB[0] = *(const float4*)&Zrow[TILE_N];
    zbB[0] = *(const float4*)&Zrow[TILE_N + 4];
#pragma unroll
    for (int c = 0; c < 5; c++)
        wB[0][c] = *(const ull*)&Wcol[NM1 + 20 * c];

#pragma unroll 2
    for (int dd = 1; dd < MPRI - 1; dd++) {
        const int cur = (dd - 1) & 1;
        const int nxt = dd & 1;
        // issue next iteration's loads first (hide 29-cyc LDS latency)
        zaB[nxt] = *(const float4*)&Zrow[(dd + 1) * TILE_N];
        zbB[nxt] = *(const float4*)&Zrow[(dd + 1) * TILE_N + 4];
#pragma unroll
        for (int c = 0; c < 5; c++)
            wB[nxt][c] = *(const ull*)&Wcol[(dd + 1) * NM1 + 20 * c];

        ull z2[8];
        z2[0] = pack2(zaB[cur].x, zaB[cur].x);
        z2[1] = pack2(zaB[cur].y, zaB[cur].y);
        z2[2] = pack2(zaB[cur].z, zaB[cur].z);
        z2[3] = pack2(zaB[cur].w, zaB[cur].w);
        z2[4] = pack2(zbB[cur].x, zbB[cur].x);
        z2[5] = pack2(zbB[cur].y, zbB[cur].y);
        z2[6] = pack2(zbB[cur].z, zbB[cur].z);
        z2[7] = pack2(zbB[cur].w, zbB[cur].w);
#pragma unroll
        for (int c = 0; c < 5; c++) {
            const ull w = wB[cur][c];
#pragma unroll
            for (int r = 0; r < 8; r++)
                acc[r][c] = fma2(z2[r], w, acc[r][c]);
        }
    }

    // tail: dd = 64 sits in buffer (MPRI-2)&1 == 1
    {
        const int cur = (MPRI - 2) & 1;
        ull z2[8];
        z2[0] = pack2(zaB[cur].x, zaB[cur].x);
        z2[1] = pack2(zaB[cur].y, zaB[cur].y);
        z2[2] = pack2(zaB[cur].z, zaB[cur].z);
        z2[3] = pack2(zaB[cur].w, zaB[cur].w);
        z2[4] = pack2(zbB[cur].x, zbB[cur].x);
        z2[5] = pack2(zbB[cur].y, zbB[cur].y);
        z2[6] = pack2(zbB[cur].z, zbB[cur].z);
        z2[7] = pack2(zbB[cur].w, zbB[cur].w);
#pragma unroll
        for (int c = 0; c < 5; c++) {
            const ull w = wB[cur][c];
#pragma unroll
            for (int r = 0; r < 8; r++)
                acc[r][c] = fma2(z2[r], w, acc[r][c]);
        }
    }

    // Store: out[n*10000 + m*100 + 2*tx + 20*c], 8-byte vector stores
#pragma unroll
    for (int r = 0; r < 8; r++) {
        long long row = (long long)(n0 + ty * 8 + r) * (NM0 * NM1)
                      + (long long)m * NM1 + 2 * tx;
#pragma unroll
        for (int c = 0; c < 5; c++)
            *(ull*)&out[row + 20 * c] = acc[r][c];
    }
}

// ---------------------------------------------------------------------------
extern "C" void kernel_launch(void* const* d_in, const int* in_sizes, int n_in,
                              void* d_out, int out_size) {
    const float* x     = (const float*)d_in[0];   // (16384, 17) f32
    const float* ms_vs = (const float*)d_in[1];   // (2306,) f32
    float* out = (float*)d_out;

    cudaFuncSetAttribute(main_kernel,
                         cudaFuncAttributeMaxDynamicSharedMemorySize, SMEM_BYTES);

    int prep_threads = EPS0_TOT + EPS1_TOT;       // 115300
    prep_kernel<<<(prep_threads + 255) / 256, 256>>>(ms_vs, out);

    dim3 grid(NROWS / TILE_N, NM0);
    main_kernel<<<grid, NTH, SMEM_BYTES>>>(x, out);
}

// round 9
// speedup vs baseline: 1.5624x; 1.0831x over previous
#include <cuda_runtime.h>
#include <cstdint>

#define NROWS 16384
#define DDIM  17          // DATA_DIM + 1
#define DH    64
#define LENM  1088
#define MPRI  65
#define NM0   100
#define NM1   100
#define TILE_N 128
#define NTH    320

typedef unsigned long long ull;

// Scratch for sampled weights (device globals — no allocation allowed)
__device__ float g_W0t[NM0 * LENM];   // [m][d*64+h]
__device__ float g_W1[MPRI * NM1];    // [d][c]

// ---------------------------------------------------------------------------
// Packed fp32x2 helpers (Blackwell FFMA2 — only reachable via PTX)
// ---------------------------------------------------------------------------
__device__ __forceinline__ ull fma2(ull a, ull b, ull c) {
    ull d;
    asm("fma.rn.f32x2 %0, %1, %2, %3;" : "=l"(d) : "l"(a), "l"(b), "l"(c));
    return d;
}
__device__ __forceinline__ ull pack2(float lo, float hi) {
    ull d;
    asm("mov.b64 %0, {%1, %2};" : "=l"(d) : "f"(lo), "f"(hi));
    return d;
}
__device__ __forceinline__ float2 unpack2(ull v) {
    float2 r;
    asm("mov.b64 {%0, %1}, %2;" : "=f"(r.x), "=f"(r.y) : "l"(v));
    return r;
}

// ---------------------------------------------------------------------------
// Threefry-2x32 (exact JAX algorithm, partitionable mode)
// ---------------------------------------------------------------------------
__device__ __forceinline__ uint32_t rotl32(uint32_t v, int r) {
    return (v << r) | (v >> (32 - r));
}

__device__ __forceinline__ void threefry2x32(uint32_t k0, uint32_t k1,
                                             uint32_t x0, uint32_t x1,
                                             uint32_t& o0, uint32_t& o1) {
    uint32_t k2 = k0 ^ k1 ^ 0x1BD11BDAu;
    x0 += k0; x1 += k1;
#define TF_R(r) { x0 += x1; x1 = rotl32(x1, (r)); x1 ^= x0; }
    TF_R(13) TF_R(15) TF_R(26) TF_R(6)
    x0 += k1; x1 += k2 + 1u;
    TF_R(17) TF_R(29) TF_R(16) TF_R(24)
    x0 += k2; x1 += k0 + 2u;
    TF_R(13) TF_R(15) TF_R(26) TF_R(6)
    x0 += k0; x1 += k1 + 3u;
    TF_R(17) TF_R(29) TF_R(16) TF_R(24)
    x0 += k1; x1 += k2 + 4u;
    TF_R(13) TF_R(15) TF_R(26) TF_R(6)
    x0 += k2; x1 += k0 + 5u;
#undef TF_R
    o0 = x0; o1 = x1;
}

__device__ __forceinline__ uint32_t random_bits_part(uint32_t k0, uint32_t k1, uint32_t i) {
    uint32_t o0, o1;
    threefry2x32(k0, k1, 0u, i, o0, o1);
    return o0 ^ o1;
}

// XLA's f32 ErfInv polynomial (Giles)
__device__ __forceinline__ float erfinv_xla(float x) {
    float w = -log1pf(-x * x);
    float p;
    if (w < 5.0f) {
        w -= 2.5f;
        p = 2.81022636e-08f;
        p = fmaf(p, w, 3.43273939e-07f);
        p = fmaf(p, w, -3.5233877e-06f);
        p = fmaf(p, w, -4.39150654e-06f);
        p = fmaf(p, w, 0.00021858087f);
        p = fmaf(p, w, -0.00125372503f);
        p = fmaf(p, w, -0.00417768164f);
        p = fmaf(p, w, 0.246640727f);
        p = fmaf(p, w, 1.50140941f);
    } else {
        w = sqrtf(w) - 3.0f;
        p = -0.000200214257f;
        p = fmaf(p, w, 0.000100950558f);
        p = fmaf(p, w, 0.00134934322f);
        p = fmaf(p, w, -0.00367342844f);
        p = fmaf(p, w, 0.00573950773f);
        p = fmaf(p, w, -0.0076224613f);
        p = fmaf(p, w, 0.00943887047f);
        p = fmaf(p, w, 1.00167406f);
        p = fmaf(p, w, 2.83297682f);
    }
    return p * x;
}

__device__ __forceinline__ float bits_to_normal(uint32_t b) {
    float f = __uint_as_float((b >> 9) | 0x3f800000u) - 1.0f;
    const float lo = -0.99999994f;
    const float diff = 2.0f;
    float u = fmaf(f, diff, lo);
    u = fmaxf(u, lo);
    return 1.41421356f * erfinv_xla(u);
}

// ---------------------------------------------------------------------------
// Prep kernel: sample W0, W1 via partitionable threefry; write output tail
// ---------------------------------------------------------------------------
#define EPS0_TOT (LENM * NM0)     // 108800
#define EPS1_TOT (MPRI * NM1)     // 6500

__global__ void prep_kernel(const float* __restrict__ ms_vs, float* __restrict__ out) {
    int tid = blockIdx.x * blockDim.x + threadIdx.x;

    uint32_t k0a, k0b, k1a, k1b;
    threefry2x32(0u, 42u, 0u, 0u, k0a, k0b);   // subkey 0
    threefry2x32(0u, 42u, 0u, 1u, k1a, k1b);   // subkey 1

    if (tid < EPS0_TOT) {
        int r = tid / NM0, m = tid % NM0;
        uint32_t b = random_bits_part(k0a, k0b, (uint32_t)tid);
        float v = fabsf(ms_vs[LENM + MPRI + r]) + 1e-6f;
        g_W0t[m * LENM + r] = fmaf(bits_to_normal(b), sqrtf(v), ms_vs[r]);
    } else if (tid < EPS0_TOT + EPS1_TOT) {
        int i = tid - EPS0_TOT;
        int r = i / NM1, c = i % NM1;
        uint32_t b = random_bits_part(k1a, k1b, (uint32_t)i);
        float v = fabsf(ms_vs[2 * LENM + MPRI + r]) + 1e-6f;
        g_W1[r * NM1 + c] = fmaf(bits_to_normal(b), sqrtf(v), ms_vs[LENM + r]);
    }

    long long base = (long long)NROWS * NM0 * NM1;
    if (tid < LENM) {
        out[base + tid]        = ms_vs[tid];
        out[base + LENM + tid] = fabsf(ms_vs[LENM + MPRI + tid]) + 1e-6f;
    }
    if (tid < MPRI) {
        out[base + 2 * LENM + tid]        = ms_vs[LENM + tid];
        out[base + 2 * LENM + MPRI + tid] = fabsf(ms_vs[2 * LENM + MPRI + tid]) + 1e-6f;
    }
}

// ---------------------------------------------------------------------------
// Main kernel: one block per (n-tile of 128, m). 320 threads, 3 CTAs/SM.
// Phase A: Z = relu(x @ W0_m), 256 threads x 16 h-pairs each (FFMA2).
// Phase B: 128x100 FFMA2 GEMM, 4 rows x 5 col-pairs per thread.
// ---------------------------------------------------------------------------
#define SMEM_FLOATS (TILE_N * DDIM + DDIM * DH + MPRI * NM1 + MPRI * TILE_N)
#define SMEM_BYTES  (SMEM_FLOATS * 4)

extern __shared__ float sm_buf[];

__global__ __launch_bounds__(NTH, 3) void main_kernel(const float* __restrict__ x,
                                                      float* __restrict__ out) {
    float* xs  = sm_buf;                      // [128][17]
    float* W0s = xs + TILE_N * DDIM;          // [17][64]
    float* W1s = W0s + DDIM * DH;             // [65][100]
    float* Zs  = W1s + MPRI * NM1;            // [65][128], row 0 = ones

    const int m   = blockIdx.y;
    const int n0  = blockIdx.x * TILE_N;
    const int tid = threadIdx.x;

    // Stage inputs (coalesced)
    for (int i = tid; i < TILE_N * DDIM; i += NTH)
        xs[i] = x[n0 * DDIM + i];
    for (int i = tid; i < LENM; i += NTH)
        W0s[i] = g_W0t[m * LENM + i];         // [d][h], h contiguous
    for (int i = tid; i < MPRI * NM1; i += NTH)
        W1s[i] = g_W1[i];
    for (int i = tid; i < TILE_N; i += NTH)
        Zs[i] = 1.0f;                          // bias row
    __syncthreads();

    // Phase A: 256 threads. thread -> (row = tid&127, h-pair segment of 16).
    if (tid < 256) {
        const int row = tid & 127;
        const int seg = tid >> 7;              // 0 or 1
        ull xr2[DDIM];
#pragma unroll
        for (int d = 0; d < DDIM; d++) {
            float v = xs[row * DDIM + d];
            xr2[d] = pack2(v, v);
        }
        const int p0 = seg * 16;
#pragma unroll 4
        for (int p = p0; p < p0 + 16; p++) {
            ull a = 0ULL;
#pragma unroll
            for (int d = 0; d < DDIM; d++)
                a = fma2(xr2[d], *(const ull*)&W0s[d * DH + 2 * p], a);
            float2 r = unpack2(a);
            Zs[(1 + 2 * p) * TILE_N + row] = fmaxf(r.x, 0.0f);
            Zs[(2 + 2 * p) * TILE_N + row] = fmaxf(r.y, 0.0f);
        }
    }
    __syncthreads();

    // Phase B: 4 rows x 5 col-pairs per thread (acc = 40 regs).
    const int tx = tid % 10;        // col-pair group: cols 2*tx + 20*c
    const int ty = tid / 10;        // 0..31 -> rows 4*ty .. 4*ty+3
    const float* Zrow = &Zs[4 * ty];
    const float* Wcol = &W1s[2 * tx];

    ull acc[4][5];
#pragma unroll
    for (int c = 0; c < 5; c++) {
        ull w0 = *(const ull*)&Wcol[20 * c];   // ones-row contribution
#pragma unroll
        for (int r = 0; r < 4; r++) acc[r][c] = w0;
    }

#pragma unroll 2
    for (int dd = 1; dd < MPRI; dd++) {
        const float4 z = *(const float4*)&Zrow[dd * TILE_N];   // LDS.128
        ull z2[4];
        z2[0] = pack2(z.x, z.x);
        z2[1] = pack2(z.y, z.y);
        z2[2] = pack2(z.z, z.z);
        z2[3] = pack2(z.w, z.w);
        const float* wrow = &Wcol[dd * NM1];
#pragma unroll
        for (int c = 0; c < 5; c++) {
            const ull w = *(const ull*)&wrow[20 * c];          // LDS.64
#pragma unroll
            for (int r = 0; r < 4; r++)
                acc[r][c] = fma2(z2[r], w, acc[r][c]);
        }
    }

    // Store: out[n*10000 + m*100 + 2*tx + 20*c], 8-byte vector stores
#pragma unroll
    for (int r = 0; r < 4; r++) {
        long long row = (long long)(n0 + 4 * ty + r) * (NM0 * NM1)
                      + (long long)m * NM1 + 2 * tx;
#pragma unroll
        for (int c = 0; c < 5; c++)
            *(ull*)&out[row + 20 * c] = acc[r][c];
    }
}

// ---------------------------------------------------------------------------
extern "C" void kernel_launch(void* const* d_in, const int* in_sizes, int n_in,
                              void* d_out, int out_size) {
    const float* x     = (const float*)d_in[0];   // (16384, 17) f32
    const float* ms_vs = (const float*)d_in[1];   // (2306,) f32
    float* out = (float*)d_out;

    cudaFuncSetAttribute(main_kernel,
                         cudaFuncAttributeMaxDynamicSharedMemorySize, SMEM_BYTES);

    int prep_threads = EPS0_TOT + EPS1_TOT;       // 115300
    prep_kernel<<<(prep_threads + 255) / 256, 256>>>(ms_vs, out);

    dim3 grid(NROWS / TILE_N, NM0);
    main_kernel<<<grid, NTH, SMEM_BYTES>>>(x, out);
}

// round 11
// speedup vs baseline: 1.5699x; 1.0048x over previous
#include <cuda_runtime.h>
#include <cstdint>

#define NROWS 16384
#define DDIM  17          // DATA_DIM + 1
#define DH    64
#define LENM  1088
#define MPRI  65
#define NM0   100
#define NM1   100
#define TILE_N 128
#define NTH    320

typedef unsigned long long ull;

// Scratch for sampled weights (device globals — no allocation allowed)
__device__ float g_W0t[NM0 * LENM];   // [m][d*64+h]
__device__ float g_W1[MPRI * NM1];    // [d][c]

// ---------------------------------------------------------------------------
// Packed fp32x2 helpers (Blackwell FFMA2 — only reachable via PTX)
// ---------------------------------------------------------------------------
__device__ __forceinline__ ull fma2(ull a, ull b, ull c) {
    ull d;
    asm("fma.rn.f32x2 %0, %1, %2, %3;" : "=l"(d) : "l"(a), "l"(b), "l"(c));
    return d;
}
__device__ __forceinline__ ull pack2(float lo, float hi) {
    ull d;
    asm("mov.b64 %0, {%1, %2};" : "=l"(d) : "f"(lo), "f"(hi));
    return d;
}
__device__ __forceinline__ float2 unpack2(ull v) {
    float2 r;
    asm("mov.b64 {%0, %1}, %2;" : "=f"(r.x), "=f"(r.y) : "l"(v));
    return r;
}

// ---------------------------------------------------------------------------
// Threefry-2x32 (exact JAX algorithm, partitionable mode)
// ---------------------------------------------------------------------------
__device__ __forceinline__ uint32_t rotl32(uint32_t v, int r) {
    return (v << r) | (v >> (32 - r));
}

__device__ __forceinline__ void threefry2x32(uint32_t k0, uint32_t k1,
                                             uint32_t x0, uint32_t x1,
                                             uint32_t& o0, uint32_t& o1) {
    uint32_t k2 = k0 ^ k1 ^ 0x1BD11BDAu;
    x0 += k0; x1 += k1;
#define TF_R(r) { x0 += x1; x1 = rotl32(x1, (r)); x1 ^= x0; }
    TF_R(13) TF_R(15) TF_R(26) TF_R(6)
    x0 += k1; x1 += k2 + 1u;
    TF_R(17) TF_R(29) TF_R(16) TF_R(24)
    x0 += k2; x1 += k0 + 2u;
    TF_R(13) TF_R(15) TF_R(26) TF_R(6)
    x0 += k0; x1 += k1 + 3u;
    TF_R(17) TF_R(29) TF_R(16) TF_R(24)
    x0 += k1; x1 += k2 + 4u;
    TF_R(13) TF_R(15) TF_R(26) TF_R(6)
    x0 += k2; x1 += k0 + 5u;
#undef TF_R
    o0 = x0; o1 = x1;
}

__device__ __forceinline__ uint32_t random_bits_part(uint32_t k0, uint32_t k1, uint32_t i) {
    uint32_t o0, o1;
    threefry2x32(k0, k1, 0u, i, o0, o1);
    return o0 ^ o1;
}

// XLA's f32 ErfInv polynomial (Giles)
__device__ __forceinline__ float erfinv_xla(float x) {
    float w = -log1pf(-x * x);
    float p;
    if (w < 5.0f) {
        w -= 2.5f;
        p = 2.81022636e-08f;
        p = fmaf(p, w, 3.43273939e-07f);
        p = fmaf(p, w, -3.5233877e-06f);
        p = fmaf(p, w, -4.39150654e-06f);
        p = fmaf(p, w, 0.00021858087f);
        p = fmaf(p, w, -0.00125372503f);
        p = fmaf(p, w, -0.00417768164f);
        p = fmaf(p, w, 0.246640727f);
        p = fmaf(p, w, 1.50140941f);
    } else {
        w = sqrtf(w) - 3.0f;
        p = -0.000200214257f;
        p = fmaf(p, w, 0.000100950558f);
        p = fmaf(p, w, 0.00134934322f);
        p = fmaf(p, w, -0.00367342844f);
        p = fmaf(p, w, 0.00573950773f);
        p = fmaf(p, w, -0.0076224613f);
        p = fmaf(p, w, 0.00943887047f);
        p = fmaf(p, w, 1.00167406f);
        p = fmaf(p, w, 2.83297682f);
    }
    return p * x;
}

__device__ __forceinline__ float bits_to_normal(uint32_t b) {
    float f = __uint_as_float((b >> 9) | 0x3f800000u) - 1.0f;
    const float lo = -0.99999994f;
    const float diff = 2.0f;
    float u = fmaf(f, diff, lo);
    u = fmaxf(u, lo);
    return 1.41421356f * erfinv_xla(u);
}

// ---------------------------------------------------------------------------
// Prep kernel: sample W0, W1 via partitionable threefry; write output tail
// ---------------------------------------------------------------------------
#define EPS0_TOT (LENM * NM0)     // 108800
#define EPS1_TOT (MPRI * NM1)     // 6500

__global__ void prep_kernel(const float* __restrict__ ms_vs, float* __restrict__ out) {
    int tid = blockIdx.x * blockDim.x + threadIdx.x;

    uint32_t k0a, k0b, k1a, k1b;
    threefry2x32(0u, 42u, 0u, 0u, k0a, k0b);   // subkey 0
    threefry2x32(0u, 42u, 0u, 1u, k1a, k1b);   // subkey 1

    if (tid < EPS0_TOT) {
        int r = tid / NM0, m = tid % NM0;
        uint32_t b = random_bits_part(k0a, k0b, (uint32_t)tid);
        float v = fabsf(ms_vs[LENM + MPRI + r]) + 1e-6f;
        g_W0t[m * LENM + r] = fmaf(bits_to_normal(b), sqrtf(v), ms_vs[r]);
    } else if (tid < EPS0_TOT + EPS1_TOT) {
        int i = tid - EPS0_TOT;
        int r = i / NM1, c = i % NM1;
        uint32_t b = random_bits_part(k1a, k1b, (uint32_t)i);
        float v = fabsf(ms_vs[2 * LENM + MPRI + r]) + 1e-6f;
        g_W1[r * NM1 + c] = fmaf(bits_to_normal(b), sqrtf(v), ms_vs[LENM + r]);
    }

    long long base = (long long)NROWS * NM0 * NM1;
    if (tid < LENM) {
        out[base + tid]        = ms_vs[tid];
        out[base + LENM + tid] = fabsf(ms_vs[LENM + MPRI + tid]) + 1e-6f;
    }
    if (tid < MPRI) {
        out[base + 2 * LENM + tid]        = ms_vs[LENM + tid];
        out[base + 2 * LENM + MPRI + tid] = fabsf(ms_vs[2 * LENM + MPRI + tid]) + 1e-6f;
    }
}

// ---------------------------------------------------------------------------
// Main kernel: one block per (n-tile of 128, m). 320 threads, 3 CTAs/SM.
// Phase A: Z = relu(x @ W0_m); x straight from global (L2-resident),
//          W0 h-quads via LDS.128 broadcast (halved LDS count).
// Phase B: 128x100 FFMA2 GEMM, 4 rows x 5 col-pairs per thread.
// ---------------------------------------------------------------------------
#define SMEM_FLOATS (DDIM * DH + MPRI * NM1 + MPRI * TILE_N)
#define SMEM_BYTES  (SMEM_FLOATS * 4)

extern __shared__ float sm_buf[];

__global__ __launch_bounds__(NTH, 3) void main_kernel(const float* __restrict__ x,
                                                      float* __restrict__ out) {
    float* W0s = sm_buf;                      // [17][64]
    float* W1s = W0s + DDIM * DH;             // [65][100]
    float* Zs  = W1s + MPRI * NM1;            // [65][128], row 0 = ones

    const int m   = blockIdx.y;
    const int n0  = blockIdx.x * TILE_N;
    const int tid = threadIdx.x;

    // Stage weights (coalesced)
    for (int i = tid; i < LENM; i += NTH)
        W0s[i] = g_W0t[m * LENM + i];         // [d][h], h contiguous
    for (int i = tid; i < MPRI * NM1; i += NTH)
        W1s[i] = g_W1[i];
    for (int i = tid; i < TILE_N; i += NTH)
        Zs[i] = 1.0f;                          // bias row
    __syncthreads();

    // Phase A: 256 threads -> (row = tid&127, seg = tid>>7 owns 8 h-quads).
    // x read per-thread from global (L2); W0 via 16B broadcast loads.
    if (tid < 256) {
        const int row = tid & 127;
        const int seg = tid >> 7;              // 0 or 1
        const float* xr = x + (long long)(n0 + row) * DDIM;
        ull xr2[DDIM];
#pragma unroll
        for (int d = 0; d < DDIM; d++) {
            float v = __ldg(&xr[d]);
            xr2[d] = pack2(v, v);
        }
#pragma unroll 2
        for (int q = seg * 8; q < seg * 8 + 8; q++) {    // h-quad 4q..4q+3
            ull a0 = 0ULL, a1 = 0ULL;
#pragma unroll
            for (int d = 0; d < DDIM; d++) {
                const ulonglong2 W = *(const ulonglong2*)&W0s[d * DH + 4 * q];
                a0 = fma2(xr2[d], W.x, a0);
                a1 = fma2(xr2[d], W.y, a1);
            }
            float2 r0 = unpack2(a0), r1 = unpack2(a1);
            const int h = 4 * q;
            Zs[(1 + h) * TILE_N + row] = fmaxf(r0.x, 0.0f);
            Zs[(2 + h) * TILE_N + row] = fmaxf(r0.y, 0.0f);
            Zs[(3 + h) * TILE_N + row] = fmaxf(r1.x, 0.0f);
            Zs[(4 + h) * TILE_N + row] = fmaxf(r1.y, 0.0f);
        }
    }
    __syncthreads();

    // Phase B: 4 rows x 5 col-pairs per thread (acc = 40 regs).
    const int tx = tid % 10;        // col-pair group: cols 2*tx + 20*c
    const int ty = tid / 10;        // 0..31 -> rows 4*ty .. 4*ty+3
    const float* Zrow = &Zs[4 * ty];
    const float* Wcol = &W1s[2 * tx];

    ull acc[4][5];
#pragma unroll
    for (int c = 0; c < 5; c++) {
        ull w0 = *(const ull*)&Wcol[20 * c];   // ones-row contribution
#pragma unroll
        for (int r = 0; r < 4; r++) acc[r][c] = w0;
    }

#pragma unroll 2
    for (int dd = 1; dd < MPRI; dd++) {
        const float4 z = *(const float4*)&Zrow[dd * TILE_N];   // LDS.128
        ull z2[4];
        z2[0] = pack2(z.x, z.x);
        z2[1] = pack2(z.y, z.y);
        z2[2] = pack2(z.z, z.z);
        z2[3] = pack2(z.w, z.w);
        const float* wrow = &Wcol[dd * NM1];
#pragma unroll
        for (int c = 0; c < 5; c++) {
            const ull w = *(const ull*)&wrow[20 * c];          // LDS.64
#pragma unroll
            for (int r = 0; r < 4; r++)
                acc[r][c] = fma2(z2[r], w, acc[r][c]);
        }
    }

    // Store: out[n*10000 + m*100 + 2*tx + 20*c], 8-byte vector stores
#pragma unroll
    for (int r = 0; r < 4; r++) {
        long long row = (long long)(n0 + 4 * ty + r) * (NM0 * NM1)
                      + (long long)m * NM1 + 2 * tx;
#pragma unroll
        for (int c = 0; c < 5; c++)
            *(ull*)&out[row + 20 * c] = acc[r][c];
    }
}

// ---------------------------------------------------------------------------
extern "C" void kernel_launch(void* const* d_in, const int* in_sizes, int n_in,
                              void* d_out, int out_size) {
    const float* x     = (const float*)d_in[0];   // (16384, 17) f32
    const float* ms_vs = (const float*)d_in[1];   // (2306,) f32
    float* out = (float*)d_out;

    cudaFuncSetAttribute(main_kernel,
                         cudaFuncAttributeMaxDynamicSharedMemorySize, SMEM_BYTES);

    int prep_threads = EPS0_TOT + EPS1_TOT;       // 115300
    prep_kernel<<<(prep_threads + 255) / 256, 256>>>(ms_vs, out);

    dim3 grid(NROWS / TILE_N, NM0);
    main_kernel<<<grid, NTH, SMEM_BYTES>>>(x, out);
}